// round 1
// baseline (speedup 1.0000x reference)
#include <cuda_runtime.h>
#include <math.h>

// Problem dims (fixed by the reference)
#define BB 4
#define LL 1024
#define DD 1024
#define HH 16
#define HDD 64
#define MM (BB * LL)   // 4096

// Scratch in device globals (allocation is forbidden).
__device__ float g_q[BB * HH * LL * HDD];
__device__ float g_k[BB * HH * LL * HDD];
__device__ float g_v[BB * HH * LL * HDD];
__device__ float g_o[BB * HH * LL * HDD];

// Index helper: MODE 0 = plain row-major [M, D]; MODE 1 = [B, H, L, HD] layout
// where m = b*L + l and the D-axis index splits as (h, d).
template <int MODE>
__device__ __forceinline__ int io_index(int m, int k) {
    if (MODE == 0) {
        return m * DD + k;
    } else {
        int b = m >> 10;          // m / L
        int l = m & 1023;         // m % L
        int h = k >> 6;           // k / HD
        int d = k & 63;           // k % HD
        return (((b * HH + h) * LL) + l) * HDD + d;
    }
}

// C[M,N] = A[M,K] * W[N,K]^T + bias[N]   (torch Linear convention)
// 64x64 tile, BK=16, 256 threads, 4x4 micro-tile with strided mapping.
template <int IN_MODE, int OUT_MODE>
__global__ __launch_bounds__(256) void gemm_kernel(
    const float* __restrict__ A, const float* __restrict__ W,
    const float* __restrict__ bias, float* __restrict__ C)
{
    __shared__ float As[64][20];   // pad 20: float4-aligned rows, 2-way max conflict
    __shared__ float Bs[64][20];

    const int m0 = blockIdx.y << 6;
    const int n0 = blockIdx.x << 6;
    const int tid = threadIdx.x;
    const int tx = tid & 15;
    const int ty = tid >> 4;
    const int lr = tid >> 2;          // load row 0..63
    const int lc = (tid & 3) << 2;    // load col {0,4,8,12}

    float acc[4][4] = {};

    for (int k0 = 0; k0 < DD; k0 += 16) {
        // Prefetch into registers before the barrier.
        const float4 av = *(const float4*)(A + io_index<IN_MODE>(m0 + lr, k0 + lc));
        const float4 bv = *(const float4*)(W + (n0 + lr) * DD + (k0 + lc));
        __syncthreads();
        *(float4*)&As[lr][lc] = av;
        *(float4*)&Bs[lr][lc] = bv;
        __syncthreads();

        #pragma unroll
        for (int kk = 0; kk < 16; ++kk) {
            float a[4], b[4];
            #pragma unroll
            for (int i = 0; i < 4; ++i) a[i] = As[ty + 16 * i][kk];
            #pragma unroll
            for (int j = 0; j < 4; ++j) b[j] = Bs[tx + 16 * j][kk];
            #pragma unroll
            for (int i = 0; i < 4; ++i)
                #pragma unroll
                for (int j = 0; j < 4; ++j)
                    acc[i][j] = fmaf(a[i], b[j], acc[i][j]);
        }
    }

    float bj[4];
    #pragma unroll
    for (int j = 0; j < 4; ++j) bj[j] = bias[n0 + tx + 16 * j];

    #pragma unroll
    for (int i = 0; i < 4; ++i) {
        const int m = m0 + ty + 16 * i;
        #pragma unroll
        for (int j = 0; j < 4; ++j) {
            const int n = n0 + tx + 16 * j;
            C[io_index<OUT_MODE>(m, n)] = acc[i][j] + bj[j];
        }
    }
}

// Flash attention over [B*H] heads, 64-row q tiles, HD = 64, causal.
// Shared: Qs[64][64], Ks[64][68], Vs[64][64], Ps[64][64]  (dynamic, 66560 B)
__global__ __launch_bounds__(256) void attn_kernel()
{
    extern __shared__ float sm[];
    float* Qs = sm;                     // 64*64
    float* Ks = Qs + 64 * 64;           // 64*68 (padded)
    float* Vs = Ks + 64 * 68;           // 64*64
    float* Ps = Vs + 64 * 64;           // 64*64

    const int bh = blockIdx.y;
    const int qt = blockIdx.x;
    const int q0 = qt << 6;

    const float* __restrict__ Qg = g_q + bh * (LL * HDD);
    const float* __restrict__ Kg = g_k + bh * (LL * HDD);
    const float* __restrict__ Vg = g_v + bh * (LL * HDD);

    const int tid = threadIdx.x;
    const int tx = tid & 15;
    const int ty = tid >> 4;

    // Load Q tile [64 x 64]
    for (int idx = tid; idx < 64 * 16; idx += 256) {
        const int r = idx >> 4;
        const int c4 = (idx & 15) << 2;
        *(float4*)&Qs[r * 64 + c4] = *(const float4*)&Qg[(q0 + r) * HDD + c4];
    }

    float acc[4][4] = {};
    float mrow[4], lrow[4];
    #pragma unroll
    for (int i = 0; i < 4; ++i) { mrow[i] = -1e30f; lrow[i] = 0.0f; }

    for (int kt = 0; kt <= qt; ++kt) {
        const int k0 = kt << 6;

        __syncthreads();   // previous PV done reading Vs/Ps before overwrite
        for (int idx = tid; idx < 64 * 16; idx += 256) {
            const int r = idx >> 4;
            const int c4 = (idx & 15) << 2;
            *(float4*)&Ks[r * 68 + c4] = *(const float4*)&Kg[(k0 + r) * HDD + c4];
            *(float4*)&Vs[r * 64 + c4] = *(const float4*)&Vg[(k0 + r) * HDD + c4];
        }
        __syncthreads();

        // S = Q K^T  (64-deep inner product)
        float s[4][4] = {};
        #pragma unroll 8
        for (int d = 0; d < 64; ++d) {
            float a[4], b[4];
            #pragma unroll
            for (int i = 0; i < 4; ++i) a[i] = Qs[(ty + 16 * i) * 64 + d];
            #pragma unroll
            for (int j = 0; j < 4; ++j) b[j] = Ks[(tx + 16 * j) * 68 + d];
            #pragma unroll
            for (int i = 0; i < 4; ++i)
                #pragma unroll
                for (int j = 0; j < 4; ++j)
                    s[i][j] = fmaf(a[i], b[j], s[i][j]);
        }

        // Scale + causal mask
        #pragma unroll
        for (int i = 0; i < 4; ++i) {
            const int qi = q0 + ty + 16 * i;
            #pragma unroll
            for (int j = 0; j < 4; ++j) {
                const int ki = k0 + tx + 16 * j;
                s[i][j] = (ki <= qi) ? s[i][j] * 0.125f : -1e30f;
            }
        }

        // Online softmax per row (rows shared across 16 tx lanes of the half-warp)
        #pragma unroll
        for (int i = 0; i < 4; ++i) {
            float mx = fmaxf(fmaxf(s[i][0], s[i][1]), fmaxf(s[i][2], s[i][3]));
            #pragma unroll
            for (int off = 8; off >= 1; off >>= 1)
                mx = fmaxf(mx, __shfl_xor_sync(0xffffffffu, mx, off));
            const float mnew = fmaxf(mrow[i], mx);
            const float alpha = __expf(mrow[i] - mnew);
            float rsum = 0.0f;
            #pragma unroll
            for (int j = 0; j < 4; ++j) {
                const float p = __expf(s[i][j] - mnew);
                s[i][j] = p;
                rsum += p;
            }
            #pragma unroll
            for (int off = 8; off >= 1; off >>= 1)
                rsum += __shfl_xor_sync(0xffffffffu, rsum, off);
            lrow[i] = lrow[i] * alpha + rsum;
            mrow[i] = mnew;
            #pragma unroll
            for (int j = 0; j < 4; ++j) acc[i][j] *= alpha;
        }

        // Stage P to shared for the cross-thread PV reduction
        #pragma unroll
        for (int i = 0; i < 4; ++i)
            #pragma unroll
            for (int j = 0; j < 4; ++j)
                Ps[(ty + 16 * i) * 64 + tx + 16 * j] = s[i][j];
        __syncthreads();

        // O += P V
        #pragma unroll 8
        for (int c = 0; c < 64; ++c) {
            float a[4], b[4];
            #pragma unroll
            for (int i = 0; i < 4; ++i) a[i] = Ps[(ty + 16 * i) * 64 + c];
            #pragma unroll
            for (int j = 0; j < 4; ++j) b[j] = Vs[c * 64 + tx + 16 * j];
            #pragma unroll
            for (int i = 0; i < 4; ++i)
                #pragma unroll
                for (int j = 0; j < 4; ++j)
                    acc[i][j] = fmaf(a[i], b[j], acc[i][j]);
        }
    }

    // Normalize and write [B,H,L,HD]
    float* Og = g_o + bh * (LL * HDD);
    #pragma unroll
    for (int i = 0; i < 4; ++i) {
        const float inv = 1.0f / lrow[i];
        #pragma unroll
        for (int j = 0; j < 4; ++j)
            Og[(q0 + ty + 16 * i) * 64 + tx + 16 * j] = acc[i][j] * inv;
    }
}

extern "C" void kernel_launch(void* const* d_in, const int* in_sizes, int n_in,
                              void* d_out, int out_size)
{
    (void)in_sizes; (void)n_in; (void)out_size;

    const float* key   = (const float*)d_in[0];
    const float* value = (const float*)d_in[1];
    const float* query = (const float*)d_in[2];
    const float* Wk    = (const float*)d_in[3];
    const float* bk    = (const float*)d_in[4];
    const float* Wq    = (const float*)d_in[5];
    const float* bq    = (const float*)d_in[6];
    const float* Wv    = (const float*)d_in[7];
    const float* bv    = (const float*)d_in[8];
    const float* Wp    = (const float*)d_in[9];
    const float* bp    = (const float*)d_in[10];
    float* out = (float*)d_out;

    float *q_p, *k_p, *v_p, *o_p;
    cudaGetSymbolAddress((void**)&q_p, g_q);
    cudaGetSymbolAddress((void**)&k_p, g_k);
    cudaGetSymbolAddress((void**)&v_p, g_v);
    cudaGetSymbolAddress((void**)&o_p, g_o);

    const dim3 grid(DD / 64, MM / 64);   // (16, 64)

    // Projections -> [B,H,L,HD]
    gemm_kernel<0, 1><<<grid, 256>>>(query, Wq, bq, q_p);
    gemm_kernel<0, 1><<<grid, 256>>>(key,   Wk, bk, k_p);
    gemm_kernel<0, 1><<<grid, 256>>>(value, Wv, bv, v_p);

    // Attention
    constexpr int SMEM = (64 * 64 + 64 * 68 + 64 * 64 + 64 * 64) * (int)sizeof(float); // 66560
    cudaFuncSetAttribute(attn_kernel, cudaFuncAttributeMaxDynamicSharedMemorySize, SMEM);
    attn_kernel<<<dim3(LL / 64, BB * HH), 256, SMEM>>>();

    // Output projection: gather [B,H,L,HD] -> [B,L,D], times Wp^T + bp
    gemm_kernel<1, 0><<<grid, 256>>>(o_p, Wp, bp, out);
}